// round 1
// baseline (speedup 1.0000x reference)
#include <cuda_runtime.h>
#include <math.h>

#define HIDDEN 1024
#define NINTER 256
#define WINDOW 64

// scratch for the MLP hidden layer (allocation-free rule: __device__ global)
__device__ float g_p[NINTER];

// ---------------------------------------------------------------------------
// Kernel 1: p[i] = tanh( dot(fc1_w[i,:], h_t) + fc1_b[i] ), one block per row.
// fp64 accumulation so the downstream ceil/floor window boundary matches the
// reference's true value as closely as possible.
// ---------------------------------------------------------------------------
__global__ void mlp1_kernel(const float* __restrict__ ht,
                            const float* __restrict__ fc1_w,
                            const float* __restrict__ fc1_b) {
    const int row  = blockIdx.x;
    const int tid  = threadIdx.x;      // 256 threads, each handles 4 elems
    const int lane = tid & 31;
    const int wid  = tid >> 5;

    float4 w = ((const float4*)(fc1_w + (size_t)row * HIDDEN))[tid];
    float4 h = ((const float4*)ht)[tid];
    double acc = (double)w.x * h.x + (double)w.y * h.y
               + (double)w.z * h.z + (double)w.w * h.w;

    #pragma unroll
    for (int o = 16; o > 0; o >>= 1)
        acc += __shfl_down_sync(0xffffffffu, acc, o);

    __shared__ double s[8];
    if (lane == 0) s[wid] = acc;
    __syncthreads();
    if (tid == 0) {
        double z = 0.0;
        #pragma unroll
        for (int i = 0; i < 8; i++) z += s[i];
        z += (double)fc1_b[row];
        g_p[row] = (float)tanh(z);
    }
}

// ---------------------------------------------------------------------------
// Kernel 2: every block redundantly computes p_t -> (ws, we, e_t), then does
// the windowed row-sum for its 64-column tile.
//   grid = 16 blocks (16 x 64 = 1024 columns), block = 512 threads:
//   tid%64 -> column within tile (coalesced 256B segments),
//   tid/64 -> row group (8 groups striding the <=129-row window).
// ---------------------------------------------------------------------------
__global__ void windowsum_kernel(const float* __restrict__ hs,
                                 const float* __restrict__ fc2_w,
                                 const float* __restrict__ fc2_b,
                                 float* __restrict__ out, int S) {
    __shared__ float sh_et;
    __shared__ int   sh_ws, sh_we;
    __shared__ float partial[8][64];

    const int tid = threadIdx.x;

    if (tid < 32) {
        double z = 0.0;
        #pragma unroll
        for (int i = tid; i < NINTER; i += 32)
            z += (double)g_p[i] * (double)fc2_w[i];
        #pragma unroll
        for (int o = 16; o > 0; o >>= 1)
            z += __shfl_down_sync(0xffffffffu, z, o);
        if (tid == 0) {
            z += (double)fc2_b[0];
            double pt = (double)S / (1.0 + exp(-z));
            double wsd = ceil(pt - (double)WINDOW);
            if (wsd < 0.0) wsd = 0.0;
            double wed = floor(pt + (double)WINDOW);
            if (wed > (double)(S - 1)) wed = (double)(S - 1);
            sh_ws = (int)wsd;
            sh_we = (int)wed;
            sh_et = (float)exp(((double)S - pt) / 2048.0);
        }
    }
    __syncthreads();

    const int   ws = sh_ws;
    const int   we = sh_we;
    const float et = sh_et;

    const int col = blockIdx.x * 64 + (tid & 63);
    const int grp = tid >> 6;                 // 0..7
    const float* base = hs + col;

    float a0 = 0.f, a1 = 0.f, a2 = 0.f, a3 = 0.f;
    int r = ws + grp;
    // unroll-4: 4 independent in-flight loads per thread (rows stride 8)
    for (; r + 24 <= we; r += 32) {
        a0 += base[(size_t)(r)      * HIDDEN];
        a1 += base[(size_t)(r + 8)  * HIDDEN];
        a2 += base[(size_t)(r + 16) * HIDDEN];
        a3 += base[(size_t)(r + 24) * HIDDEN];
    }
    for (; r <= we; r += 8)
        a0 += base[(size_t)r * HIDDEN];

    partial[grp][tid & 63] = (a0 + a1) + (a2 + a3);
    __syncthreads();

    if (tid < 64) {
        float s = 0.f;
        #pragma unroll
        for (int g = 0; g < 8; g++) s += partial[g][tid];
        out[col] = et * s;
    }
}

extern "C" void kernel_launch(void* const* d_in, const int* in_sizes, int n_in,
                              void* d_out, int out_size) {
    const float* hs    = (const float*)d_in[0];
    const float* ht    = (const float*)d_in[1];
    const float* fc1_w = (const float*)d_in[2];
    const float* fc1_b = (const float*)d_in[3];
    const float* fc2_w = (const float*)d_in[4];
    const float* fc2_b = (const float*)d_in[5];

    const int S = in_sizes[0] / HIDDEN;   // host-side, capture-safe

    mlp1_kernel<<<NINTER, 256>>>(ht, fc1_w, fc1_b);
    windowsum_kernel<<<16, 512>>>(hs, fc2_w, fc2_b, (float*)d_out, S);
}